// round 9
// baseline (speedup 1.0000x reference)
#include <cuda_runtime.h>
#include <math.h>

#define BB 8
#define TT 256
#define UU 64
#define VV 512
#define U1 65
#define BS 66                 // diag-row stride for blank
#define DR 320                // diag rows per batch (t+u in [0,319])
#define NEGF (-1e30f)
#define LOG2E 1.4426950408889634f
#define LN2   0.6931471805599453f
#define ROWS_PER_BATCH (TT * U1)    // 16640
#define BLOCKS_PER_BATCH 2080       // 16640 rows / 8 rows per block
#define ROWS_PER_CHUNK 2080         // 32 t-values * 65
#define BLOCKS_PER_CHUNK 260
#define NCHUNK 8

// Diagonal-major scratch (log2 domain). element (t,u) lives at diag row t+u,
// col u. Unwritten slots stay 0 from .bss zero-init (never written) and act
// as the guard zeros of the branch-free DP recurrence.
__device__ float g_blank_d[BB * DR * BS];
__device__ float g_emit_d [BB * DR * UU];
__device__ float g_loss   [BB];
__device__ int   g_chunk  [BB * NCHUNK];  // producer progress; self-resets
__device__ int   g_fin;                   // finalize ticket; self-resets

__device__ __forceinline__ float ex2_fast(float x)
{
    float r; asm("ex2.approx.ftz.f32 %0, %1;" : "=f"(r) : "f"(x)); return r;
}
__device__ __forceinline__ float lg2_fast(float x)
{
    float r; asm("lg2.approx.f32 %0, %1;" : "=f"(r) : "f"(x)); return r;
}

// log2-domain logaddexp, pure MUFU; lae2(NEGF, y) == y bit-exact
// (ex2 of -1e30 flushes to 0, lg2(1) == 0).
__device__ __forceinline__ float lae2(float x, float y)
{
    const float mm = fmaxf(x, y);
    const float e  = x - y;
    return mm + lg2_fast(1.f + ex2_fast(0.f - fabsf(e)));
}

// ---------------------------------------------------------------------------
// Fused kernel. Blocks 0..7: DP consumers (one warp each). Blocks 8..16647:
// softmax producers (8 warps = 8 rows each; chunk-aligned).
// ---------------------------------------------------------------------------
__global__ void __launch_bounds__(256) rnnt_fused_kernel(
    const float* __restrict__ pred, const int* __restrict__ target,
    const int* __restrict__ pred_len, const int* __restrict__ target_len,
    float* __restrict__ out)
{
    __shared__ float s_cum[320];   // alpha[t][0] (log2); only DP blocks use it

    if (blockIdx.x >= BB) {
        // ================= softmax producer =================
        const int r    = (blockIdx.x - BB) * 8 + (threadIdx.x >> 5);
        const int lane = threadIdx.x & 31;

        const int b   = r / ROWS_PER_BATCH;
        const int rem = r % ROWS_PER_BATCH;
        const int t   = rem / U1;
        const int u   = rem % U1;

        const float* rowp  = pred + (size_t)r * VV;
        const float4* row4 = reinterpret_cast<const float4*>(rowp);

        const int tgt = (u < UU) ? target[b * UU + u] : 0;
        const float ev = __ldg(rowp + tgt);

        float4 v0 = row4[lane];
        float4 v1 = row4[lane + 32];
        float4 v2 = row4[lane + 64];
        float4 v3 = row4[lane + 96];

        float m = fmaxf(fmaxf(fmaxf(v0.x, v0.y), fmaxf(v0.z, v0.w)),
                        fmaxf(fmaxf(v1.x, v1.y), fmaxf(v1.z, v1.w)));
        m = fmaxf(m, fmaxf(fmaxf(fmaxf(v2.x, v2.y), fmaxf(v2.z, v2.w)),
                           fmaxf(fmaxf(v3.x, v3.y), fmaxf(v3.z, v3.w))));
        #pragma unroll
        for (int o = 16; o > 0; o >>= 1) m = fmaxf(m, __shfl_xor_sync(0xffffffffu, m, o));

        float s = 0.f;
        s += ex2_fast((v0.x - m) * LOG2E) + ex2_fast((v0.y - m) * LOG2E)
           + ex2_fast((v0.z - m) * LOG2E) + ex2_fast((v0.w - m) * LOG2E);
        s += ex2_fast((v1.x - m) * LOG2E) + ex2_fast((v1.y - m) * LOG2E)
           + ex2_fast((v1.z - m) * LOG2E) + ex2_fast((v1.w - m) * LOG2E);
        s += ex2_fast((v2.x - m) * LOG2E) + ex2_fast((v2.y - m) * LOG2E)
           + ex2_fast((v2.z - m) * LOG2E) + ex2_fast((v2.w - m) * LOG2E);
        s += ex2_fast((v3.x - m) * LOG2E) + ex2_fast((v3.y - m) * LOG2E)
           + ex2_fast((v3.z - m) * LOG2E) + ex2_fast((v3.w - m) * LOG2E);
        #pragma unroll
        for (int o = 16; o > 0; o >>= 1) s += __shfl_xor_sync(0xffffffffu, s, o);

        if (lane == 0) {
            const float lse2 = m * LOG2E + lg2_fast(s);
            const int dgr = b * DR + t + u;             // diag row
            g_blank_d[dgr * BS + u] = v0.x * LOG2E - lse2;
            if (u < UU)
                g_emit_d[dgr * UU + u] = ev * LOG2E - lse2;
        }

        __syncthreads();
        if (threadIdx.x == 0) {
            __threadfence();
            const int r0 = (blockIdx.x - BB) * 8;
            const int bb = r0 / ROWS_PER_BATCH;
            const int cc = (r0 % ROWS_PER_BATCH) / ROWS_PER_CHUNK;
            atomicAdd(&g_chunk[bb * NCHUNK + cc], 1);
        }
        return;
    }

    // ================= DP consumer (one warp) =================
    if (threadIdx.x >= 32) return;
    const int b    = blockIdx.x;
    const int lane = threadIdx.x;

    for (int i = lane; i < 320; i += 32) s_cum[i] = 0.f;

    const int pl = pred_len[b];
    const int tl = target_len[b];

    const float* gb = g_blank_d + b * DR * BS;
    const float* ge = g_emit_d  + b * DR * UU;
    volatile int* cnt = g_chunk + b * NCHUNK;

    float v1 = NEGF, v2 = NEGF, res1 = 0.f, res2 = 0.f;
    const int  src = (lane + 31) & 31;   // wrapped up-neighbor (lane0 <- lane31)
    const bool l0  = (lane == 0);

    const int dm = pl - 1 + tl;
    const int dmatch1 = (lane + 1  == tl) ? dm : -1;
    const int dmatch2 = (lane + 33 == tl) ? dm : -1;

    float carry = 0.f;
    int next_c = 0;
    int ibl = lane + 1;   // blank diag (d-1)*BS + (lane+1), starting d=1
    int iem = lane;       // emit  diag (d-1)*UU + lane

    for (int k = 0; k < 10; ++k) {
        const int need = (k < 7) ? k : 7;
        while (next_c <= need) {
            if (l0) { while (cnt[next_c] < BLOCKS_PER_CHUNK) __nanosleep(128); }
            __syncwarp();
            __threadfence();
            // extend u=0 cumsum for t = 32*next_c + lane (diag row t, col 0)
            const float bv = gb[(32 * next_c + lane) * BS];
            float inc = bv;
            #pragma unroll
            for (int o = 1; o < 32; o <<= 1) {
                const float n = __shfl_up_sync(0xffffffffu, inc, o);
                if (lane >= o) inc += n;
            }
            s_cum[32 * next_c + lane] = carry + inc - bv;   // exclusive
            carry += __shfl_sync(0xffffffffu, inc, 31);
            ++next_c;
        }

        const int dend = (k == 9) ? 319 : (32 * k + 32);
        #pragma unroll 4
        for (int d = 32 * k + 1; d <= dend; ++d) {
            const float a1 = __shfl_sync(0xffffffffu, v1, src);
            const float a2 = __shfl_sync(0xffffffffu, v2, src);
            const float cumv = s_cum[d - 1];

            const float bl1 = __ldg(gb + ibl);
            const float em1 = __ldg(ge + iem);
            const float bl2 = __ldg(gb + ibl + 32);
            const float em2 = __ldg(ge + iem + 32);
            ibl += BS; iem += UU;

            const float x1 = v1 + bl1;
            const float y1 = (l0 ? cumv : a1) + em1;
            const float x2 = v2 + bl2;
            const float y2 = (l0 ? a1 : a2) + em2;   // lane0's u=33 needs u=32

            v1 = lae2(x1, y1);
            v2 = lae2(x2, y2);

            res1 = (d == dmatch1) ? v1 : res1;
            res2 = (d == dmatch2) ? v2 : res2;
        }
    }

    const float final_blank = gb[(pl - 1 + tl) * BS + tl];
    const float rsel = (tl >= 33) ? res2 : res1;
    const int   srcl = (tl >= 33) ? (tl - 33) : (tl - 1);
    const float rv = __shfl_sync(0xffffffffu, rsel, srcl);

    if (l0) {
        g_loss[b] = rv + final_blank;
        #pragma unroll
        for (int c = 0; c < NCHUNK; ++c) cnt[c] = 0;   // self-reset for replay
        __threadfence();
        const int tkt = atomicAdd(&g_fin, 1);
        if (tkt == BB - 1) {
            __threadfence();
            float ssum = 0.f;
            #pragma unroll
            for (int q = 0; q < BB; ++q) ssum += g_loss[q];
            out[0] = -ssum * (LN2 / (float)BB);
            g_fin = 0;                                  // self-reset
        }
    }
}

extern "C" void kernel_launch(void* const* d_in, const int* in_sizes, int n_in,
                              void* d_out, int out_size)
{
    const float* pred       = (const float*)d_in[0];
    const int*   target     = (const int*)  d_in[1];
    const int*   pred_len   = (const int*)  d_in[2];
    const int*   target_len = (const int*)  d_in[3];
    float*       out        = (float*)      d_out;

    (void)in_sizes; (void)n_in; (void)out_size;

    const int softmax_blocks = (BB * ROWS_PER_BATCH) / 8;   // 16640
    rnnt_fused_kernel<<<BB + softmax_blocks, 256>>>(
        pred, target, pred_len, target_len, out);
}

// round 11
// speedup vs baseline: 2.5387x; 2.5387x over previous
#include <cuda_runtime.h>
#include <math.h>

#define BB 8
#define TT 256
#define UU 64
#define VV 512
#define U1 (UU + 1)
#define BSTRIDE 66            // padded blank row stride
#define GROWS 64              // guard rows before/after
#define BROWS (GROWS + TT + GROWS)   // 384
#define NEGF (-1e30f)
#define LOG2E 1.4426950408889634f
#define LN2   0.6931471805599453f

// Scratch (allocation-free rule: __device__ globals). Log2 domain.
__device__ float g_blank[BB * TT * U1];   // log2_probs[..., 0]
__device__ float g_emit [BB * TT * UU];   // log2_probs[b,t,u,target[b,u]]
__device__ float g_loss [BB];             // log2-domain final alpha+blank
__device__ int   g_fin;                   // finalize ticket; self-resets

// Raw MUFU intrinsics (guaranteed single-instruction regardless of fast-math)
__device__ __forceinline__ float ex2_fast(float x)
{
    float r; asm("ex2.approx.ftz.f32 %0, %1;" : "=f"(r) : "f"(x)); return r;
}
__device__ __forceinline__ float lg2_fast(float x)
{
    float r; asm("lg2.approx.f32 %0, %1;" : "=f"(r) : "f"(x)); return r;
}

// ---------------------------------------------------------------------------
// Kernel 1: per-row logsumexp over V=512 -> blank/emit log2-probs.
// One warp per (b,t,u) row; emit via direct gather (L1 hit).
// ---------------------------------------------------------------------------
__global__ void __launch_bounds__(256) rnnt_softmax_kernel(
    const float* __restrict__ pred, const int* __restrict__ target)
{
    const int warp = (blockIdx.x * blockDim.x + threadIdx.x) >> 5;
    const int lane = threadIdx.x & 31;
    const int rows = BB * TT * U1;
    if (warp >= rows) return;

    const int b   = warp / (TT * U1);
    const int rem = warp % (TT * U1);
    const int t   = rem / U1;
    const int u   = rem % U1;

    const float* rowp = pred + (size_t)warp * VV;
    const float4* row4 = reinterpret_cast<const float4*>(rowp);

    // emit gather (issued early; independent of the bulk stream)
    const int tgt = (u < UU) ? target[b * UU + u] : 0;
    const float ev = __ldg(rowp + tgt);

    float4 v0 = row4[lane];
    float4 v1 = row4[lane + 32];
    float4 v2 = row4[lane + 64];
    float4 v3 = row4[lane + 96];

    float m = fmaxf(fmaxf(fmaxf(v0.x, v0.y), fmaxf(v0.z, v0.w)),
                    fmaxf(fmaxf(v1.x, v1.y), fmaxf(v1.z, v1.w)));
    m = fmaxf(m, fmaxf(fmaxf(fmaxf(v2.x, v2.y), fmaxf(v2.z, v2.w)),
                       fmaxf(fmaxf(v3.x, v3.y), fmaxf(v3.z, v3.w))));
    #pragma unroll
    for (int o = 16; o > 0; o >>= 1) m = fmaxf(m, __shfl_xor_sync(0xffffffffu, m, o));

    float s = 0.f;
    s += ex2_fast((v0.x - m) * LOG2E) + ex2_fast((v0.y - m) * LOG2E)
       + ex2_fast((v0.z - m) * LOG2E) + ex2_fast((v0.w - m) * LOG2E);
    s += ex2_fast((v1.x - m) * LOG2E) + ex2_fast((v1.y - m) * LOG2E)
       + ex2_fast((v1.z - m) * LOG2E) + ex2_fast((v1.w - m) * LOG2E);
    s += ex2_fast((v2.x - m) * LOG2E) + ex2_fast((v2.y - m) * LOG2E)
       + ex2_fast((v2.z - m) * LOG2E) + ex2_fast((v2.w - m) * LOG2E);
    s += ex2_fast((v3.x - m) * LOG2E) + ex2_fast((v3.y - m) * LOG2E)
       + ex2_fast((v3.z - m) * LOG2E) + ex2_fast((v3.w - m) * LOG2E);
    #pragma unroll
    for (int o = 16; o > 0; o >>= 1) s += __shfl_xor_sync(0xffffffffu, s, o);

    if (lane == 0) {
        const float lse2 = m * LOG2E + lg2_fast(s);
        g_blank[warp] = v0.x * LOG2E - lse2;
        if (u < UU)
            g_emit[b * TT * UU + t * UU + u] = ev * LOG2E - lse2;
    }
}

// log2-domain logaddexp, pure MUFU; lae2(NEGF, y) == y bit-exact
// (ex2 of a hugely negative arg flushes to 0, lg2(1) == 0).
__device__ __forceinline__ float lae2(float x, float y)
{
    const float mm = fmaxf(x, y);
    const float e  = x - y;
    return mm + lg2_fast(1.f + ex2_fast(0.f - fabsf(e)));
}

// ---------------------------------------------------------------------------
// Kernel 2: branch-free warp-synchronous wavefront DP, one warp per batch,
// paired-u mapping: lane owns u_A = 2*lane+1, u_B = 2*lane+2.
//   cell B's left neighbor = cell A same lane (register)  -> 1 shfl/iter only
//   cell A's left neighbor = cell B of lane-1 (shfl)
// u=0 column precomputed as a prefix sum (s_cum). Guard-padded smem tiles.
// Finalize (mean) folded in via atomic ticket.
// ---------------------------------------------------------------------------
__global__ void __launch_bounds__(256) rnnt_dp_kernel(
    const int* __restrict__ pred_len, const int* __restrict__ target_len,
    float* __restrict__ out)
{
    extern __shared__ float sm[];
    float* s_blank = sm;                       // BROWS * BSTRIDE floats
    float* s_emit  = sm + BROWS * BSTRIDE;     // BROWS * UU floats
    __shared__ float s_cum[320];               // alpha[t][0] (log2), padded

    const int b   = blockIdx.x;
    const int tid = threadIdx.x;

    // Zero guards + cum padding (256 threads)
    for (int i = tid; i < GROWS * BSTRIDE; i += 256) {
        s_blank[i] = 0.f;
        s_blank[(GROWS + TT) * BSTRIDE + i] = 0.f;
    }
    for (int i = tid; i < GROWS * UU; i += 256) {
        s_emit[i] = 0.f;
        s_emit[(GROWS + TT) * UU + i] = 0.f;
    }
    for (int i = tid; i < 320; i += 256) s_cum[i] = 0.f;
    // Center fills
    for (int i = tid; i < TT * U1; i += 256) {
        const int t = i / U1, u = i - t * U1;
        s_blank[(GROWS + t) * BSTRIDE + u] = g_blank[b * TT * U1 + i];
    }
    {
        const float4* src4 = reinterpret_cast<const float4*>(g_emit + b * TT * UU);
        float4* dst4 = reinterpret_cast<float4*>(s_emit + GROWS * UU);
        for (int i = tid; i < TT * UU / 4; i += 256) dst4[i] = src4[i];
    }
    __syncthreads();

    if (tid >= 32) return;
    const int lane = tid;
    const int pl = pred_len[b];
    const int tl = target_len[b];
    const float final_blank = s_blank[(GROWS + pl - 1) * BSTRIDE + tl];

    // ---- u=0 column: exclusive prefix sum of blank[t][0] (warp scan) ----
    {
        float carry = 0.f;
        #pragma unroll
        for (int c = 0; c < 8; ++c) {
            const float bv = s_blank[(GROWS + c * 32 + lane) * BSTRIDE];
            float inc = bv;
            #pragma unroll
            for (int o = 1; o < 32; o <<= 1) {
                const float n = __shfl_up_sync(0xffffffffu, inc, o);
                if (lane >= o) inc += n;
            }
            s_cum[c * 32 + lane] = carry + inc - bv;   // exclusive
            carry += __shfl_sync(0xffffffffu, inc, 31);
        }
    }

    // ---- wavefront, paired u: uA = 2*lane+1, uB = 2*lane+2 ----
    const int uA = 2 * lane + 1;
    const int uB = 2 * lane + 2;
    float vA = NEGF, vB = NEGF;
    // index walks (at d=1): blank row (d-1-u), col u ; emit row (d-u), col u-1
    int ibA = (GROWS - uA) * BSTRIDE + uA;       // (d-1-uA)+GROWS row at d=1
    int ieA = (GROWS + 1 - uA) * UU + uA - 1;
    const int  src = (lane + 31) & 31;           // wrapped left-neighbor lane
    const bool l0  = (lane == 0);

    const int dm = pl - 1 + tl;                  // tl in [56,64], never 0
    const int dmatchA = (uA == tl) ? dm : -1;
    const int dmatchB = (uB == tl) ? dm : -1;
    float resA = 0.f, resB = 0.f;

    #pragma unroll 4
    for (int d = 1; d < TT + UU; ++d) {
        const float nB = __shfl_sync(0xffffffffu, vB, src);  // prev-diag u = uA-1
        const float cumv = s_cum[d - 1];
        const float aOld = vA;                               // prev-diag u = uB-1

        const float blA = s_blank[ibA];
        const float emA = s_emit [ieA];
        const float blB = s_blank[ibA - BSTRIDE + 1];        // row-1, col+1
        const float emB = s_emit [ieA - UU + 1];
        ibA += BSTRIDE; ieA += UU;

        const float xA = vA + blA;
        const float yA = (l0 ? cumv : nB) + emA;
        vA = lae2(xA, yA);

        const float xB = vB + blB;
        const float yB = aOld + emB;
        vB = lae2(xB, yB);

        resA = (d == dmatchA) ? vA : resA;
        resB = (d == dmatchB) ? vB : resB;
    }

    if (dmatchA >= 0) g_loss[b] = resA + final_blank;
    if (dmatchB >= 0) g_loss[b] = resB + final_blank;
    __syncwarp();

    // ---- finalize ticket (last DP block computes the mean) ----
    if (l0) {
        __threadfence();
        const int tkt = atomicAdd(&g_fin, 1);
        if (tkt == BB - 1) {
            __threadfence();
            float ssum = 0.f;
            #pragma unroll
            for (int q = 0; q < BB; ++q) ssum += g_loss[q];
            out[0] = -ssum * (LN2 / (float)BB);
            g_fin = 0;                                  // self-reset for replay
        }
    }
}

extern "C" void kernel_launch(void* const* d_in, const int* in_sizes, int n_in,
                              void* d_out, int out_size)
{
    const float* pred       = (const float*)d_in[0];
    const int*   target     = (const int*)  d_in[1];
    const int*   pred_len   = (const int*)  d_in[2];
    const int*   target_len = (const int*)  d_in[3];
    float*       out        = (float*)      d_out;

    (void)in_sizes; (void)n_in; (void)out_size;

    const int rows   = BB * TT * U1;               // 133120 rows
    const int wpb    = 256 / 32;                   // 8 warps per block
    const int blocks = (rows + wpb - 1) / wpb;     // 16640

    const int smem_bytes = (BROWS * BSTRIDE + BROWS * UU) * (int)sizeof(float); // 199680
    cudaFuncSetAttribute(rnnt_dp_kernel,
                         cudaFuncAttributeMaxDynamicSharedMemorySize, smem_bytes);

    rnnt_softmax_kernel<<<blocks, 256>>>(pred, target);
    rnnt_dp_kernel<<<BB, 256, smem_bytes>>>(pred_len, target_len, out);
}

// round 14
// speedup vs baseline: 2.6887x; 1.0591x over previous
#include <cuda_runtime.h>
#include <math.h>

#define BB 8
#define TT 256
#define UU 64
#define VV 512
#define U1 (UU + 1)
#define DR 320                // diag rows per batch (t+u in 0..319)
#define BS 66                 // blank diag-row stride (col = u+1, even stride)
#define ES 64                 // emit diag-row stride (col = u)
#define NEGF (-1e30f)
#define LOG2E 1.4426950408889634f
#define LN2   0.6931471805599453f

// Diag-major scratch (log2 domain). blank(t,u) -> [b][t+u][u+1]; emit(t,u) ->
// [b][t+u][u]. Unwritten slots stay 0 from .bss (never stored to) and act as
// the guard zeros of the branch-free DP recurrence.
__device__ float g_blank_d[BB * DR * BS];
__device__ float g_emit_d [BB * DR * ES];
__device__ float g_loss   [BB];
__device__ int   g_fin;                   // finalize ticket; self-resets

__device__ __forceinline__ float ex2_fast(float x)
{
    float r; asm("ex2.approx.ftz.f32 %0, %1;" : "=f"(r) : "f"(x)); return r;
}
__device__ __forceinline__ float lg2_fast(float x)
{
    float r; asm("lg2.approx.f32 %0, %1;" : "=f"(r) : "f"(x)); return r;
}

// log2-domain logaddexp, pure MUFU; lae2(NEGF, y) == y bit-exact.
__device__ __forceinline__ float lae2(float x, float y)
{
    const float mm = fmaxf(x, y);
    const float e  = x - y;
    return mm + lg2_fast(1.f + ex2_fast(0.f - fabsf(e)));
}

// ---------------------------------------------------------------------------
// Kernel 1: per-row logsumexp over V=512 -> blank/emit log2-probs, written
// DIAG-MAJOR. One warp per (b,t,u) row; emit via direct gather.
// ---------------------------------------------------------------------------
__global__ void __launch_bounds__(256) rnnt_softmax_kernel(
    const float* __restrict__ pred, const int* __restrict__ target)
{
    const int warp = (blockIdx.x * blockDim.x + threadIdx.x) >> 5;
    const int lane = threadIdx.x & 31;
    const int rows = BB * TT * U1;
    if (warp >= rows) return;

    const int b   = warp / (TT * U1);
    const int rem = warp % (TT * U1);
    const int t   = rem / U1;
    const int u   = rem % U1;

    const float* rowp = pred + (size_t)warp * VV;
    const float4* row4 = reinterpret_cast<const float4*>(rowp);

    const int tgt = (u < UU) ? target[b * UU + u] : 0;
    const float ev = __ldg(rowp + tgt);

    float4 v0 = row4[lane];
    float4 v1 = row4[lane + 32];
    float4 v2 = row4[lane + 64];
    float4 v3 = row4[lane + 96];

    float m = fmaxf(fmaxf(fmaxf(v0.x, v0.y), fmaxf(v0.z, v0.w)),
                    fmaxf(fmaxf(v1.x, v1.y), fmaxf(v1.z, v1.w)));
    m = fmaxf(m, fmaxf(fmaxf(fmaxf(v2.x, v2.y), fmaxf(v2.z, v2.w)),
                       fmaxf(fmaxf(v3.x, v3.y), fmaxf(v3.z, v3.w))));
    #pragma unroll
    for (int o = 16; o > 0; o >>= 1) m = fmaxf(m, __shfl_xor_sync(0xffffffffu, m, o));

    float s = 0.f;
    s += ex2_fast((v0.x - m) * LOG2E) + ex2_fast((v0.y - m) * LOG2E)
       + ex2_fast((v0.z - m) * LOG2E) + ex2_fast((v0.w - m) * LOG2E);
    s += ex2_fast((v1.x - m) * LOG2E) + ex2_fast((v1.y - m) * LOG2E)
       + ex2_fast((v1.z - m) * LOG2E) + ex2_fast((v1.w - m) * LOG2E);
    s += ex2_fast((v2.x - m) * LOG2E) + ex2_fast((v2.y - m) * LOG2E)
       + ex2_fast((v2.z - m) * LOG2E) + ex2_fast((v2.w - m) * LOG2E);
    s += ex2_fast((v3.x - m) * LOG2E) + ex2_fast((v3.y - m) * LOG2E)
       + ex2_fast((v3.z - m) * LOG2E) + ex2_fast((v3.w - m) * LOG2E);
    #pragma unroll
    for (int o = 16; o > 0; o >>= 1) s += __shfl_xor_sync(0xffffffffu, s, o);

    if (lane == 0) {
        const float lse2 = m * LOG2E + lg2_fast(s);
        const int dgr = b * DR + t + u;
        g_blank_d[dgr * BS + u + 1] = v0.x * LOG2E - lse2;
        if (u < UU)
            g_emit_d[dgr * ES + u] = ev * LOG2E - lse2;
    }
}

// ---------------------------------------------------------------------------
// Kernel 2: branch-free warp-synchronous wavefront DP, one warp per batch.
// Paired-u: lane owns uA = 2*lane+1, uB = 2*lane+2 (1 shfl/iter).
// Diag-major smem: both operands of diagonal d live contiguously on diag row
// d-1 -> two aligned float2 LDS per iter, conflict-free. Straight float4 copy
// for staging. u=0 column precomputed (s_cum). Finalize via atomic ticket.
// ---------------------------------------------------------------------------
__global__ void __launch_bounds__(256) rnnt_dp_kernel(
    const int* __restrict__ pred_len, const int* __restrict__ target_len,
    float* __restrict__ out)
{
    extern __shared__ float sm[];
    float* s_blank = sm;                 // DR*BS floats (21120)
    float* s_emit  = sm + DR * BS;       // DR*ES floats (20480)
    __shared__ float s_cum[DR];          // alpha[t][0] (log2)

    const int b   = blockIdx.x;
    const int tid = threadIdx.x;

    // Straight vector copies (diag-major, guards included as zeros)
    {
        const float4* sb4 = reinterpret_cast<const float4*>(g_blank_d + b * DR * BS);
        float4* db4 = reinterpret_cast<float4*>(s_blank);
        for (int i = tid; i < DR * BS / 4; i += 256) db4[i] = sb4[i];
        const float4* se4 = reinterpret_cast<const float4*>(g_emit_d + b * DR * ES);
        float4* de4 = reinterpret_cast<float4*>(s_emit);
        for (int i = tid; i < DR * ES / 4; i += 256) de4[i] = se4[i];
    }
    for (int i = tid; i < DR; i += 256) s_cum[i] = 0.f;
    __syncthreads();

    if (tid >= 32) return;
    const int lane = tid;
    const int pl = pred_len[b];
    const int tl = target_len[b];
    // blank(pl-1, tl) -> diag row pl-1+tl, col tl+1
    const float final_blank = s_blank[(pl - 1 + tl) * BS + tl + 1];

    // ---- u=0 column: exclusive prefix sum of blank[t][0] (warp scan) ----
    // blank(t,0) lives at diag row t, col 1.
    {
        float carry = 0.f;
        #pragma unroll
        for (int c = 0; c < 8; ++c) {
            const float bv = s_blank[(c * 32 + lane) * BS + 1];
            float inc = bv;
            #pragma unroll
            for (int o = 1; o < 32; o <<= 1) {
                const float n = __shfl_up_sync(0xffffffffu, inc, o);
                if (lane >= o) inc += n;
            }
            s_cum[c * 32 + lane] = carry + inc - bv;   // exclusive = alpha[t][0]
            carry += __shfl_sync(0xffffffffu, inc, 31);
        }
    }

    // ---- wavefront, paired u: uA = 2*lane+1, uB = 2*lane+2 ----
    const int uA = 2 * lane + 1;
    const int uB = 2 * lane + 2;
    float vA = NEGF, vB = NEGF;
    const int  src = (lane + 31) & 31;   // wrapped left-neighbor lane
    const bool l0  = (lane == 0);

    const int dm = pl - 1 + tl;          // tl in [56,64]
    const int dmatchA = (uA == tl) ? dm : -1;
    const int dmatchB = (uB == tl) ? dm : -1;
    float resA = 0.f, resB = 0.f;

    // per-iter reads, all on diag row d-1:
    //   blank(t-1,uA) col uA+1 = 2L+2 ; blank(t-1,uB) col 2L+3  -> float2
    //   emit(t,uA-1)  col 2L         ; emit(t,uB-1)  col 2L+1   -> float2
    int ibl = 2 * lane + 2;              // into s_blank, row 0 at d=1
    int iem = 2 * lane;                  // into s_emit

    #pragma unroll 4
    for (int d = 1; d < TT + UU; ++d) {
        const float nB   = __shfl_sync(0xffffffffu, vB, src);  // prev-diag uA-1
        const float cumv = s_cum[d - 1];
        const float aOld = vA;                                  // prev-diag uB-1

        const float2 bl = *reinterpret_cast<const float2*>(s_blank + ibl);
        const float2 em = *reinterpret_cast<const float2*>(s_emit  + iem);
        ibl += BS; iem += ES;

        const float xA = vA + bl.x;
        const float yA = (l0 ? cumv : nB) + em.x;
        vA = lae2(xA, yA);

        const float xB = vB + bl.y;
        const float yB = aOld + em.y;
        vB = lae2(xB, yB);

        resA = (d == dmatchA) ? vA : resA;
        resB = (d == dmatchB) ? vB : resB;
    }

    if (dmatchA >= 0) g_loss[b] = resA + final_blank;
    if (dmatchB >= 0) g_loss[b] = resB + final_blank;
    __syncwarp();

    // ---- finalize ticket (last DP block computes the mean) ----
    if (l0) {
        __threadfence();
        const int tkt = atomicAdd(&g_fin, 1);
        if (tkt == BB - 1) {
            __threadfence();
            float ssum = 0.f;
            #pragma unroll
            for (int q = 0; q < BB; ++q) ssum += g_loss[q];
            out[0] = -ssum * (LN2 / (float)BB);
            g_fin = 0;                                  // self-reset for replay
        }
    }
}

extern "C" void kernel_launch(void* const* d_in, const int* in_sizes, int n_in,
                              void* d_out, int out_size)
{
    const float* pred       = (const float*)d_in[0];
    const int*   target     = (const int*)  d_in[1];
    const int*   pred_len   = (const int*)  d_in[2];
    const int*   target_len = (const int*)  d_in[3];
    float*       out        = (float*)      d_out;

    (void)in_sizes; (void)n_in; (void)out_size;

    const int rows   = BB * TT * U1;               // 133120 rows
    const int wpb    = 256 / 32;
    const int blocks = (rows + wpb - 1) / wpb;     // 16640

    const int smem_bytes = (DR * BS + DR * ES) * (int)sizeof(float); // 166400
    cudaFuncSetAttribute(rnnt_dp_kernel,
                         cudaFuncAttributeMaxDynamicSharedMemorySize, smem_bytes);

    rnnt_softmax_kernel<<<blocks, 256>>>(pred, target);
    rnnt_dp_kernel<<<BB, 256, smem_bytes>>>(pred_len, target_len, out);
}